// round 2
// baseline (speedup 1.0000x reference)
#include <cuda_runtime.h>
#include <math.h>

#define NSIG 65536
#define NAT  512
#define MDIM 64
#define KSP  5
#define NBLK 2048            // NSIG / 32 signals per block
#define SMEM_FLOATS (2048 + 16384 + 20480 + 2112)
#define SMEM_BYTES  (SMEM_FLOATS * 4)

// ---------------- device globals (scratch; no allocations allowed) ----------
__device__ __align__(16) float  g_dnormJ[MDIM][NAT];   // [m][j]
__device__ __align__(16) float  g_dnormT[NAT][MDIM];   // [j][m]
__device__ __align__(16) float  g_G[NAT][NAT];         // Gram
__device__ double g_partial[NBLK];

// ---------------- f32x2 packed-FMA helpers (Blackwell) ----------------------
__device__ __forceinline__ unsigned long long fma2(unsigned long long a,
                                                   unsigned long long b,
                                                   unsigned long long c) {
    unsigned long long r;
    asm("fma.rn.f32x2 %0, %1, %2, %3;" : "=l"(r) : "l"(a), "l"(b), "l"(c));
    return r;
}
__device__ __forceinline__ unsigned long long pack2(float x) {
    unsigned long long r;
    asm("mov.b64 %0, {%1, %1};" : "=l"(r) : "f"(x));
    return r;
}
__device__ __forceinline__ float2 unpack2(unsigned long long v) {
    float2 f;
    asm("mov.b64 {%0, %1}, %2;" : "=f"(f.x), "=f"(f.y) : "l"(v));
    return f;
}

// ---------------- K0: normalize dictionary columns --------------------------
__global__ void k_norm(const float* __restrict__ dict) {
    int j = blockIdx.x * blockDim.x + threadIdx.x;
    if (j >= NAT) return;
    float ss = 0.f;
    for (int m = 0; m < MDIM; m++) { float v = dict[m * NAT + j]; ss += v * v; }
    float nrm = fmaxf(sqrtf(ss), 1e-10f);
    for (int m = 0; m < MDIM; m++) {
        float d = dict[m * NAT + j] / nrm;
        g_dnormJ[m][j] = d;
        g_dnormT[j][m] = d;
    }
}

// ---------------- K1: Gram matrix G = Dn^T Dn --------------------------------
__global__ void k_gram() {
    __shared__ float di[MDIM];
    int i = blockIdx.x;
    if (threadIdx.x < MDIM) di[threadIdx.x] = g_dnormT[i][threadIdx.x];
    __syncthreads();
    for (int j = threadIdx.x; j < NAT; j += blockDim.x) {
        float acc = 0.f;
        #pragma unroll
        for (int m = 0; m < MDIM; m++) acc += di[m] * g_dnormJ[m][j];
        g_G[i][j] = acc;
    }
}

// ---------------- K2: zero the coeffs output (unaligned base -> scalar) -----
__global__ void k_zero(float* __restrict__ p, size_t n) {
    size_t i  = (size_t)blockIdx.x * blockDim.x + threadIdx.x;
    size_t st = (size_t)gridDim.x * blockDim.x;
    for (; i < n; i += st) p[i] = 0.f;
}

// ---------------- K3: fused h_bar GEMM + per-warp OMP + outputs -------------
__global__ void __launch_bounds__(256, 1)
k_main(const float* __restrict__ ze, float* __restrict__ out_z,
       float* __restrict__ out_coef) {
    extern __shared__ float smem[];
    float* sh_x  = smem;                    // [64][32]     2048
    float* sh_hb = smem + 2048;             // [32][512]   16384
    float* sh_g  = smem + 2048 + 16384;     // [8][5][512] 20480
    float* sh_z  = sh_g + 20480;            // [64][33]     2112 (padded)
    __shared__ double sh_red[256];

    const int tid  = threadIdx.x;
    const int lane = tid & 31;
    const int wid  = tid >> 5;
    const int tile = blockIdx.x * 32;
    const int b    = tile >> 10;
    const int hw0  = tile & 1023;
    const float* zb = ze + (size_t)b * 65536 + hw0;

    // ---- load X tile: sh_x[m][sl] (coalesced) ----
    for (int i = tid; i < 2048; i += 256) {
        int m = i >> 5, sl = i & 31;
        sh_x[i] = zb[m * 1024 + sl];
    }
    __syncthreads();

    // ---- Phase 1: h_bar[sl][j] = sum_m dnorm[m][j] * x[m][sl]  (f32x2) ----
    // thread -> 4 signals (sg = wid) x 32 atoms (j = 128*q + 4*lane + c)
    {
        unsigned long long acc[4][8];
        #pragma unroll
        for (int c = 0; c < 4; c++)
            #pragma unroll
            for (int p = 0; p < 8; p++) acc[c][p] = 0ull;

        for (int m = 0; m < MDIM; m++) {
            const ulonglong2* drow = (const ulonglong2*)(&g_dnormJ[m][0]);
            ulonglong2 d0 = drow[lane];
            ulonglong2 d1 = drow[32 + lane];
            ulonglong2 d2 = drow[64 + lane];
            ulonglong2 d3 = drow[96 + lane];
            unsigned long long dv[8] = {d0.x, d0.y, d1.x, d1.y,
                                        d2.x, d2.y, d3.x, d3.y};
            float4 xs4 = *(const float4*)(sh_x + m * 32 + wid * 4);
            float xc[4] = {xs4.x, xs4.y, xs4.z, xs4.w};
            #pragma unroll
            for (int c = 0; c < 4; c++) {
                unsigned long long xp = pack2(xc[c]);
                #pragma unroll
                for (int p = 0; p < 8; p++) acc[c][p] = fma2(dv[p], xp, acc[c][p]);
            }
        }
        #pragma unroll
        for (int c = 0; c < 4; c++) {
            float* hrow = sh_hb + (wid * 4 + c) * 512;
            #pragma unroll
            for (int q = 0; q < 4; q++) {
                float2 a  = unpack2(acc[c][2 * q]);
                float2 bb = unpack2(acc[c][2 * q + 1]);
                *(float4*)(hrow + q * 128 + lane * 4) =
                    make_float4(a.x, a.y, bb.x, bb.y);
            }
        }
    }
    __syncthreads();

    // ---- Phase 2: per-warp OMP (4 signals sequential per warp) ----
    float* myg = sh_g + wid * 5 * 512;
    for (int sc = 0; sc < 4; ++sc) {
        const int sl = wid * 4 + sc;
        const int s  = tile + sl;
        const float* hrow = sh_hb + sl * 512;

        float hb[16], h[16];
        #pragma unroll
        for (int t = 0; t < 16; t++) { hb[t] = hrow[lane + 32 * t]; h[t] = hb[t]; }

        unsigned mask16 = 0u;
        int   idxs[5];
        float xs[5], y[5], hbsel[5];
        float L[5][5];

        #pragma unroll
        for (int k = 0; k < 5; k++) {
            // ---- masked abs-argmax (first-max tie-break like jnp.argmax) ----
            float bestv = -1.f; int bestj = 0; float bhb = 0.f;
            #pragma unroll
            for (int t = 0; t < 16; t++) {
                if (!((mask16 >> t) & 1u)) {
                    float a = fabsf(h[t]);
                    if (a > bestv) { bestv = a; bestj = lane + 32 * t; bhb = hb[t]; }
                }
            }
            #pragma unroll
            for (int off = 16; off; off >>= 1) {
                float ov = __shfl_xor_sync(0xffffffffu, bestv, off);
                int   oj = __shfl_xor_sync(0xffffffffu, bestj, off);
                float ob = __shfl_xor_sync(0xffffffffu, bhb,   off);
                if (ov > bestv || (ov == bestv && oj < bestj)) {
                    bestv = ov; bestj = oj; bhb = ob;
                }
            }
            if ((bestj & 31) == lane) mask16 |= 1u << (bestj >> 5);
            idxs[k]  = bestj;
            hbsel[k] = bhb;

            // ---- prefetch new Gram row (overlaps Cholesky update) ----
            const float4* gr = (const float4*)(&g_G[bestj][0]);
            float4 gv0 = gr[lane],      gv1 = gr[lane + 32];
            float4 gv2 = gr[lane + 64], gv3 = gr[lane + 96];

            // ---- incremental Cholesky (redundant on all lanes) ----
            if (k == 0) {
                L[0][0] = 1.f;
            } else {
                float w[4];
                #pragma unroll
                for (int i = 0; i < 4; i++) if (i < k) {
                    float gi = myg[i * 512 + bestj];
                    #pragma unroll
                    for (int j2 = 0; j2 < 4; j2++) if (j2 < i) gi -= L[i][j2] * w[j2];
                    w[i] = gi / L[i][i];
                }
                float s2 = 0.f;
                #pragma unroll
                for (int i = 0; i < 4; i++) if (i < k) { L[k][i] = w[i]; s2 += w[i] * w[i]; }
                L[k][k] = sqrtf(1.f - s2);
            }

            // ---- stage new row into SMEM ----
            float4* dst = (float4*)(myg + k * 512);
            dst[lane] = gv0; dst[lane + 32] = gv1;
            dst[lane + 64] = gv2; dst[lane + 96] = gv3;
            __syncwarp();

            // ---- forward / backward triangular solves (size k+1) ----
            #pragma unroll
            for (int i = 0; i < 5; i++) if (i <= k) {
                float v = hbsel[i];
                #pragma unroll
                for (int j2 = 0; j2 < 5; j2++) if (j2 < i) v -= L[i][j2] * y[j2];
                y[i] = v / L[i][i];
            }
            #pragma unroll
            for (int i = 4; i >= 0; i--) if (i <= k) {
                float v = y[i];
                #pragma unroll
                for (int j2 = 0; j2 < 5; j2++) if (j2 > i && j2 <= k) v -= L[j2][i] * xs[j2];
                xs[i] = v / L[i][i];
            }

            // ---- residual correlation update (skipped at last iter) ----
            if (k < 4) {
                #pragma unroll
                for (int t = 0; t < 16; t++) {
                    float a = hb[t];
                    #pragma unroll
                    for (int i = 0; i < 5; i++) if (i <= k)
                        a -= xs[i] * myg[i * 512 + lane + 32 * t];
                    h[t] = a;
                }
            }
        }

        // ---- coeffs scatter (lane i writes atom i) ----
        #pragma unroll
        for (int i = 0; i < 5; i++)
            if (lane == i) out_coef[(size_t)idxs[i] * 65536 + s] = xs[i];

        // ---- sparse reconstruction, staged for coalesced write ----
        float r0 = 0.f, r1 = 0.f;
        #pragma unroll
        for (int i = 0; i < 5; i++) {
            const float* dr = &g_dnormT[idxs[i]][0];
            r0 += xs[i] * dr[lane];
            r1 += xs[i] * dr[lane + 32];
        }
        sh_z[lane * 33 + sl]        = r0;
        sh_z[(lane + 32) * 33 + sl] = r1;
    }
    __syncthreads();

    // ---- Phase 3: coalesced z_dl_st write + deterministic loss reduce ----
    double part = 0.0;
    float* oz = out_z + (size_t)b * 65536 + hw0;
    for (int i = tid; i < 2048; i += 256) {
        int m = i >> 5, sl = i & 31;
        float xv = sh_x[m * 32 + sl];
        float r  = sh_z[m * 33 + sl];
        float dd = r - xv;
        part += (double)dd * (double)dd;
        oz[m * 1024 + sl] = xv + dd;   // z_e + (z_dl - z_e)
    }
    sh_red[tid] = part;
    __syncthreads();
    for (int sft = 128; sft; sft >>= 1) {
        if (tid < sft) sh_red[tid] += sh_red[tid + sft];
        __syncthreads();
    }
    if (tid == 0) g_partial[blockIdx.x] = sh_red[0];
}

// ---------------- K4: final loss = 1.25 * mean(diff^2) ----------------------
__global__ void k_loss(float* __restrict__ out_loss) {
    __shared__ double red[256];
    double p = 0.0;
    for (int i = threadIdx.x; i < NBLK; i += 256) p += g_partial[i];
    red[threadIdx.x] = p;
    __syncthreads();
    for (int s = 128; s; s >>= 1) {
        if (threadIdx.x < s) red[threadIdx.x] += red[threadIdx.x + s];
        __syncthreads();
    }
    if (threadIdx.x == 0)
        out_loss[0] = (float)(1.25 * red[0] / 4194304.0);
}

// ---------------- launch ------------------------------------------------------
extern "C" void kernel_launch(void* const* d_in, const int* in_sizes, int n_in,
                              void* d_out, int out_size) {
    const float* ze   = (const float*)d_in[0];
    const float* dict = (const float*)d_in[1];
    float* out      = (float*)d_out;
    float* out_z    = out;                 // 4,194,304
    float* out_loss = out + 4194304;       // 1
    float* out_coef = out + 4194305;       // 33,554,432

    cudaFuncSetAttribute(k_main, cudaFuncAttributeMaxDynamicSharedMemorySize,
                         SMEM_BYTES);

    k_norm<<<2, 256>>>(dict);
    k_gram<<<NAT, 128>>>();
    k_zero<<<4096, 256>>>(out_coef, (size_t)33554432);
    k_main<<<NBLK, 256, SMEM_BYTES>>>(ze, out_z, out_coef);
    k_loss<<<1, 256>>>(out_loss);
}

// round 3
// speedup vs baseline: 1.4103x; 1.4103x over previous
#include <cuda_runtime.h>
#include <math.h>

#define NSIG 65536
#define NAT  512
#define MDIM 64
#define NBLK 2048            // NSIG / 32 signals per block
#define SMEM_FLOATS (2048 + 16384 + 2112)
#define SMEM_BYTES  (SMEM_FLOATS * 4)

// ---------------- device globals (scratch; no allocations allowed) ----------
__device__ __align__(16) float  g_dnormJ[MDIM][NAT];   // [m][j]
__device__ __align__(16) float  g_dnormT[NAT][MDIM];   // [j][m]
__device__ __align__(16) float  g_G[NAT][NAT];         // Gram
__device__ double g_partial[NBLK];

// ---------------- f32x2 packed-FMA helpers (Blackwell) ----------------------
__device__ __forceinline__ unsigned long long fma2(unsigned long long a,
                                                   unsigned long long b,
                                                   unsigned long long c) {
    unsigned long long r;
    asm("fma.rn.f32x2 %0, %1, %2, %3;" : "=l"(r) : "l"(a), "l"(b), "l"(c));
    return r;
}
__device__ __forceinline__ unsigned long long pack2(float x) {
    unsigned long long r;
    asm("mov.b64 %0, {%1, %1};" : "=l"(r) : "f"(x));
    return r;
}
__device__ __forceinline__ float2 unpack2(unsigned long long v) {
    float2 f;
    asm("mov.b64 {%0, %1}, %2;" : "=f"(f.x), "=f"(f.y) : "l"(v));
    return f;
}

// ---------------- K0: normalize dictionary columns --------------------------
__global__ void k_norm(const float* __restrict__ dict) {
    int j = blockIdx.x * blockDim.x + threadIdx.x;
    if (j >= NAT) return;
    float ss = 0.f;
    for (int m = 0; m < MDIM; m++) { float v = dict[m * NAT + j]; ss += v * v; }
    float nrm = fmaxf(sqrtf(ss), 1e-10f);
    for (int m = 0; m < MDIM; m++) {
        float d = dict[m * NAT + j] / nrm;
        g_dnormJ[m][j] = d;
        g_dnormT[j][m] = d;
    }
}

// ---------------- K1: Gram matrix G = Dn^T Dn --------------------------------
__global__ void k_gram() {
    __shared__ float di[MDIM];
    int i = blockIdx.x;
    if (threadIdx.x < MDIM) di[threadIdx.x] = g_dnormT[i][threadIdx.x];
    __syncthreads();
    for (int j = threadIdx.x; j < NAT; j += blockDim.x) {
        float acc = 0.f;
        #pragma unroll
        for (int m = 0; m < MDIM; m++) acc += di[m] * g_dnormJ[m][j];
        g_G[i][j] = acc;
    }
}

// ---------------- K3: fused zero + h_bar GEMM + per-warp OMP + outputs -------
__global__ void __launch_bounds__(256, 2)
k_main(const float* __restrict__ ze, float* __restrict__ out_z,
       float* __restrict__ out_coef) {
    extern __shared__ float smem[];
    float* sh_x  = smem;                    // [64][32]     2048
    float* sh_hb = smem + 2048;             // [32][512]   16384
    float* sh_z  = smem + 2048 + 16384;     // [64][33]     2112 (padded)
    __shared__ double sh_red[256];

    const int tid  = threadIdx.x;
    const int lane = tid & 31;
    const int wid  = tid >> 5;
    const int tile = blockIdx.x * 32;
    const int b    = tile >> 10;
    const int hw0  = tile & 1023;
    const float* zb = ze + (size_t)b * 65536 + hw0;

    // ---- zero this block's 32 coeff columns (hides under GEMM) ----
    {
        float* cz = out_coef + tile;
        for (int i = tid; i < NAT * 32; i += 256) {
            int j = i >> 5, sl = i & 31;
            cz[(size_t)j * 65536 + sl] = 0.f;
        }
    }

    // ---- load X tile: sh_x[m][sl] (coalesced) ----
    for (int i = tid; i < 2048; i += 256) {
        int m = i >> 5, sl = i & 31;
        sh_x[i] = zb[m * 1024 + sl];
    }
    __syncthreads();

    // ---- Phase 1: h_bar[sl][j] = sum_m dnorm[m][j] * x[m][sl]  (f32x2) ----
    {
        unsigned long long acc[4][8];
        #pragma unroll
        for (int c = 0; c < 4; c++)
            #pragma unroll
            for (int p = 0; p < 8; p++) acc[c][p] = 0ull;

        for (int m = 0; m < MDIM; m++) {
            const ulonglong2* drow = (const ulonglong2*)(&g_dnormJ[m][0]);
            ulonglong2 d0 = drow[lane];
            ulonglong2 d1 = drow[32 + lane];
            ulonglong2 d2 = drow[64 + lane];
            ulonglong2 d3 = drow[96 + lane];
            unsigned long long dv[8] = {d0.x, d0.y, d1.x, d1.y,
                                        d2.x, d2.y, d3.x, d3.y};
            float4 xs4 = *(const float4*)(sh_x + m * 32 + wid * 4);
            float xc[4] = {xs4.x, xs4.y, xs4.z, xs4.w};
            #pragma unroll
            for (int c = 0; c < 4; c++) {
                unsigned long long xp = pack2(xc[c]);
                #pragma unroll
                for (int p = 0; p < 8; p++) acc[c][p] = fma2(dv[p], xp, acc[c][p]);
            }
        }
        #pragma unroll
        for (int c = 0; c < 4; c++) {
            float* hrow = sh_hb + (wid * 4 + c) * 512;
            #pragma unroll
            for (int q = 0; q < 4; q++) {
                float2 a  = unpack2(acc[c][2 * q]);
                float2 bb = unpack2(acc[c][2 * q + 1]);
                *(float4*)(hrow + q * 128 + lane * 4) =
                    make_float4(a.x, a.y, bb.x, bb.y);
            }
        }
    }
    __syncthreads();

    // ---- Phase 2: per-warp OMP (4 signals sequential per warp) ----
    #pragma unroll 1
    for (int sc = 0; sc < 4; ++sc) {
        const int sl = wid * 4 + sc;
        const int s  = tile + sl;
        const float* hrow = sh_hb + sl * 512;

        float h[16];
        #pragma unroll
        for (int t = 0; t < 16; t++) h[t] = hrow[lane + 32 * t];

        unsigned mask16 = 0u;
        int   idxs[5];
        float xs[5], xsold[5], y[5], rinv[5];
        float Lm[5][5];
        float g[4][16];
        #pragma unroll
        for (int i = 0; i < 5; i++) xsold[i] = 0.f;

        #pragma unroll
        for (int k = 0; k < 5; k++) {
            // ---- packed u64 abs-argmax (value|~j|sign), first-max tie-break --
            unsigned long long key = 0ull;
            #pragma unroll
            for (int t = 0; t < 16; t++) {
                if (!((mask16 >> t) & 1u)) {
                    float hv = h[t];
                    unsigned ab  = __float_as_uint(fabsf(hv));
                    unsigned sgn = __float_as_uint(hv) >> 31;
                    int j = lane + 32 * t;
                    unsigned long long cand =
                        ((unsigned long long)ab << 32) |
                        (unsigned)(((0x3FF - j) << 1) | sgn);
                    if (cand > key) key = cand;
                }
            }
            #pragma unroll
            for (int off = 16; off; off >>= 1) {
                unsigned long long o = __shfl_xor_sync(0xffffffffu, key, off);
                if (o > key) key = o;
            }
            unsigned lo = (unsigned)key;
            int   bestj = 0x3FF - (int)(lo >> 1);
            float absv  = __uint_as_float((unsigned)(key >> 32));
            float h_sel = (lo & 1u) ? -absv : absv;
            if ((bestj & 31) == lane) mask16 |= 1u << (bestj >> 5);
            idxs[k] = bestj;

            // ---- prefetch new Gram row into registers (k<4 only) ----
            float gnew[16];
            if (k < 4) {
                const float* grow = &g_G[bestj][0];
                #pragma unroll
                for (int t = 0; t < 16; t++)
                    gnew[t] = __ldg(grow + lane + 32 * t);
            }

            // ---- G_stack scalars (L1-hot) + reconstruct hbar[bestj] ----
            float gs[4];
            #pragma unroll
            for (int i = 0; i < 4; i++) if (i < k)
                gs[i] = __ldg(&g_G[idxs[i]][bestj]);
            float hbk = h_sel;
            #pragma unroll
            for (int i = 0; i < 4; i++) if (i < k) hbk += xs[i] * gs[i];

            // ---- incremental Cholesky ----
            if (k == 0) {
                Lm[0][0] = 1.f; rinv[0] = 1.f;
            } else {
                float w[4]; float s2 = 0.f;
                #pragma unroll
                for (int i = 0; i < 4; i++) if (i < k) {
                    float v = gs[i];
                    #pragma unroll
                    for (int j2 = 0; j2 < 4; j2++) if (j2 < i) v -= Lm[i][j2] * w[j2];
                    w[i] = v * rinv[i];
                    Lm[k][i] = w[i];
                    s2 += w[i] * w[i];
                }
                Lm[k][k] = sqrtf(1.f - s2);
                rinv[k]  = __frcp_rn(Lm[k][k]);
            }

            // ---- incremental forward solve (y[0..k-1] unchanged) ----
            {
                float v = hbk;
                #pragma unroll
                for (int j2 = 0; j2 < 4; j2++) if (j2 < k) v -= Lm[k][j2] * y[j2];
                y[k] = v * rinv[k];
            }
            // ---- backward solve (size k+1) ----
            #pragma unroll
            for (int i = 4; i >= 0; i--) if (i <= k) {
                float v = y[i];
                #pragma unroll
                for (int j2 = 0; j2 < 5; j2++)
                    if (j2 > i && j2 <= k) v -= Lm[j2][i] * xs[j2];
                xs[i] = v * rinv[i];
            }

            // ---- delta residual update from registers (skip last iter) ----
            if (k < 4) {
                #pragma unroll
                for (int t = 0; t < 16; t++) g[k][t] = gnew[t];
                float dx[5];
                #pragma unroll
                for (int i = 0; i < 5; i++) if (i <= k) {
                    dx[i] = xs[i] - xsold[i];
                    xsold[i] = xs[i];
                }
                #pragma unroll
                for (int t = 0; t < 16; t++) {
                    float a = h[t];
                    #pragma unroll
                    for (int i = 0; i < 4; i++) if (i <= k) a -= dx[i] * g[i][t];
                    h[t] = a;
                }
            }
        }

        // ---- coeffs scatter (lane i writes atom i) ----
        #pragma unroll
        for (int i = 0; i < 5; i++)
            if (lane == i) out_coef[(size_t)idxs[i] * 65536 + s] = xs[i];

        // ---- sparse reconstruction, staged for coalesced write ----
        float r0 = 0.f, r1 = 0.f;
        #pragma unroll
        for (int i = 0; i < 5; i++) {
            const float* dr = &g_dnormT[idxs[i]][0];
            r0 += xs[i] * dr[lane];
            r1 += xs[i] * dr[lane + 32];
        }
        sh_z[lane * 33 + sl]        = r0;
        sh_z[(lane + 32) * 33 + sl] = r1;
    }
    __syncthreads();

    // ---- Phase 3: coalesced z_dl_st write + deterministic loss reduce ----
    double part = 0.0;
    float* oz = out_z + (size_t)b * 65536 + hw0;
    for (int i = tid; i < 2048; i += 256) {
        int m = i >> 5, sl = i & 31;
        float xv = sh_x[m * 32 + sl];
        float r  = sh_z[m * 33 + sl];
        float dd = r - xv;
        part += (double)dd * (double)dd;
        oz[m * 1024 + sl] = xv + dd;   // z_e + (z_dl - z_e)
    }
    sh_red[tid] = part;
    __syncthreads();
    for (int sft = 128; sft; sft >>= 1) {
        if (tid < sft) sh_red[tid] += sh_red[tid + sft];
        __syncthreads();
    }
    if (tid == 0) g_partial[blockIdx.x] = sh_red[0];
}

// ---------------- K4: final loss = 1.25 * mean(diff^2) ----------------------
__global__ void k_loss(float* __restrict__ out_loss) {
    __shared__ double red[256];
    double p = 0.0;
    for (int i = threadIdx.x; i < NBLK; i += 256) p += g_partial[i];
    red[threadIdx.x] = p;
    __syncthreads();
    for (int s = 128; s; s >>= 1) {
        if (threadIdx.x < s) red[threadIdx.x] += red[threadIdx.x + s];
        __syncthreads();
    }
    if (threadIdx.x == 0)
        out_loss[0] = (float)(1.25 * red[0] / 4194304.0);
}

// ---------------- launch ------------------------------------------------------
extern "C" void kernel_launch(void* const* d_in, const int* in_sizes, int n_in,
                              void* d_out, int out_size) {
    const float* ze   = (const float*)d_in[0];
    const float* dict = (const float*)d_in[1];
    float* out      = (float*)d_out;
    float* out_z    = out;                 // 4,194,304
    float* out_loss = out + 4194304;       // 1
    float* out_coef = out + 4194305;       // 33,554,432

    cudaFuncSetAttribute(k_main, cudaFuncAttributeMaxDynamicSharedMemorySize,
                         SMEM_BYTES);

    k_norm<<<2, 256>>>(dict);
    k_gram<<<NAT, 128>>>();
    k_main<<<NBLK, 256, SMEM_BYTES>>>(ze, out_z, out_coef);
    k_loss<<<1, 256>>>(out_loss);
}